// round 4
// baseline (speedup 1.0000x reference)
#include <cuda_runtime.h>
#include <stdint.h>
#include <math.h>

// Problem constants
#define NB    16
#define HW    56
#define NPIX  3136           // 56*56
#define NBP   50176          // NB*NPIX
#define C_IN  256
#define C_MID 64
#define EPSC  1e-6f
#define BNEPS 1e-5f
#define NOUT_MAIN 12845056   // 16*256*56*56
#define NG3   64225280       // 5*16*256*3136 gumbels for stage 3

// ---------------- scratch (__device__ globals; no allocation) ----------------
__device__ float g_y   [NOUT_MAIN];   // conv output (pre-BN), per stage
__device__ float g_cos1[C_MID*NBP];   // cosine stage 1
__device__ float g_cos2[C_MID*NBP];   // cosine stage 2
__device__ float g_cos3[NOUT_MAIN];   // cosine stage 3
__device__ float g_g3  [NG3];         // precomputed gumbels, stage 3
__device__ float g_h   [C_MID*NBP];   // post-BN/ReLU activations (h1, then h2)
__device__ float g_ss  [NBP];         // per-pixel sum of squares (or sqrt thereof)
__device__ float g_xn  [NBP];         // x_norm for conv2 (sqrt of 3x3 box sum)
__device__ float g_wn  [512];         // weight Frobenius norms (64 + 64 + 256)
__device__ float g_st  [768];         // BN sums/sumsq per stage
__device__ float g_acc [1];

// ---------------- f32x2 packed math ----------------
__device__ __forceinline__ void ffma2(uint64_t& d, uint64_t a, uint64_t b) {
    asm("fma.rn.f32x2 %0, %1, %2, %0;" : "+l"(d) : "l"(a), "l"(b));
}
__device__ __forceinline__ uint64_t bcast2(float w) {
    uint64_t r; asm("mov.b64 %0, {%1, %1};" : "=l"(r) : "f"(w)); return r;
}
__device__ __forceinline__ void unpack2(uint64_t v, float& lo, float& hi) {
    asm("mov.b64 {%0, %1}, %2;" : "=f"(lo), "=f"(hi) : "l"(v));
}

// ---------------- threefry2x32 (JAX-exact, partitionable mode) ----------------
__host__ __device__ __forceinline__ uint32_t rotl32(uint32_t x, int r) {
    return (x << r) | (x >> (32 - r));
}

__host__ __device__ __forceinline__ void threefry2x32(
    uint32_t k0, uint32_t k1, uint32_t c0, uint32_t c1, uint32_t& o0, uint32_t& o1)
{
    uint32_t ks0 = k0, ks1 = k1, ks2 = k0 ^ k1 ^ 0x1BD11BDAu;
    uint32_t x0 = c0 + ks0, x1 = c1 + ks1;
#define TF_R(r) { x0 += x1; x1 = rotl32(x1, r); x1 ^= x0; }
    TF_R(13) TF_R(15) TF_R(26) TF_R(6)   x0 += ks1; x1 += ks2 + 1u;
    TF_R(17) TF_R(29) TF_R(16) TF_R(24)  x0 += ks2; x1 += ks0 + 2u;
    TF_R(13) TF_R(15) TF_R(26) TF_R(6)   x0 += ks0; x1 += ks1 + 3u;
    TF_R(17) TF_R(29) TF_R(16) TF_R(24)  x0 += ks1; x1 += ks2 + 4u;
    TF_R(13) TF_R(15) TF_R(26) TF_R(6)   x0 += ks2; x1 += ks0 + 5u;
#undef TF_R
    o0 = x0; o1 = x1;
}

// Device version: rotate via widening mul (fma pipe) -> round = add + IMAD.WIDE + LOP3.
__device__ __forceinline__ void threefry2x32_dev(
    uint32_t k0, uint32_t k1, uint32_t c0, uint32_t c1, uint32_t& o0, uint32_t& o1)
{
    uint32_t ks0 = k0, ks1 = k1, ks2 = k0 ^ k1 ^ 0x1BD11BDAu;
    uint32_t x0 = c0 + ks0, x1 = c1 + ks1;
#define TF_R(r) { x0 += x1; \
    uint64_t m = (uint64_t)x1 * ((uint64_t)(1u << (r))); \
    x1 = ((uint32_t)m | (uint32_t)(m >> 32)) ^ x0; }
    TF_R(13) TF_R(15) TF_R(26) TF_R(6)   x0 += ks1; x1 += ks2 + 1u;
    TF_R(17) TF_R(29) TF_R(16) TF_R(24)  x0 += ks2; x1 += ks0 + 2u;
    TF_R(13) TF_R(15) TF_R(26) TF_R(6)   x0 += ks0; x1 += ks1 + 3u;
    TF_R(17) TF_R(29) TF_R(16) TF_R(24)  x0 += ks1; x1 += ks2 + 4u;
    TF_R(13) TF_R(15) TF_R(26) TF_R(6)   x0 += ks2; x1 += ks0 + 5u;
#undef TF_R
    o0 = x0; o1 = x1;
}

__device__ __forceinline__ float gumbel_from_bits(uint32_t bits) {
    float u = __uint_as_float(0x3f800000u | (bits >> 9)) - 1.0f;
    u = fmaxf(u, 1.17549435e-38f);
    return -__logf(-__logf(u));
}

// ---------------- combined init + weight norms ----------------
// Grid 384: rows 0-63 -> w1 (len 256); 64-127 -> w2 (len 576); 128-383 -> w3 (len 64)
__global__ void wnorm_all_k(const float* __restrict__ w1, const float* __restrict__ w2,
                            const float* __restrict__ w3) {
    __shared__ float sm[256];
    int row = blockIdx.x;
    const float* w; int len; int r;
    if (row < 64)       { w = w1; len = 256; r = row; }
    else if (row < 128) { w = w2; len = 576; r = row - 64; }
    else                { w = w3; len = 64;  r = row - 128; }
    float s = 0.0f;
    for (int i = threadIdx.x; i < len; i += 256) {
        float v = w[(long long)r * len + i];
        s += v * v;
    }
    sm[threadIdx.x] = s; __syncthreads();
    for (int st = 128; st > 0; st >>= 1) {
        if (threadIdx.x < st) sm[threadIdx.x] += sm[threadIdx.x + st];
        __syncthreads();
    }
    if (threadIdx.x == 0) g_wn[row] = sqrtf(sm[0]);
    // zero BN stat accumulators + acc (block 0)
    if (row == 0) {
        for (int i = threadIdx.x; i < 768; i += 256) g_st[i] = 0.0f;
        if (threadIdx.x == 0) g_acc[0] = 0.0f;
    }
}

// ---------------- stage-3 gumbel precompute (data-independent) ----------------
__global__ void hash3_k(uint32_t k0, uint32_t k1, float* __restrict__ g) {
    uint32_t e = blockIdx.x * 256u + threadIdx.x;
    if (e >= (uint32_t)NG3) return;
    uint32_t o0, o1;
    threefry2x32_dev(k0, k1, 0u, e, o0, o1);
    g[e] = gumbel_from_bits(o0 ^ o1);
}

// ---------------- 1x1 conv GEMM (f32x2) + cosine + fused BN stats ------------
// Block: 64 out-channels x 128 pixels.  Grid: (25, B, outC/64)
template<int CIN, bool COMPUTE_SS>
__global__ void __launch_bounds__(256) conv1x1_k(
    const float* __restrict__ X, const float* __restrict__ W,
    const float* __restrict__ wn, const float* __restrict__ xn,
    float* __restrict__ Y, float* __restrict__ COS,
    float* __restrict__ stbase, int outC)
{
    __shared__ float sX[16][128];
    __shared__ float sW[64][17];
    __shared__ float sF[128];
    __shared__ float sWF[64];

    const int tid  = threadIdx.x;
    const int p0   = blockIdx.x * 128;
    const int b    = blockIdx.y;
    const int co0  = blockIdx.z * 64;
    const int px_l = tid & 127, kk2 = tid >> 7;
    const int co_g = tid >> 5,  px_g = tid & 31;

    const float* Xb = X + (long long)b * CIN * NPIX;

    if (!COMPUTE_SS) {
        if (tid < 128) {
            int pp = p0 + tid;
            float v = (pp < NPIX) ? xn[b * NPIX + pp] : 1.0f;
            sF[tid] = 1.0f / (v + EPSC);
        }
    }
    if (tid < 64) sWF[tid] = 1.0f / (wn[co0 + tid] + EPSC);

    uint64_t acc2[8][2];
#pragma unroll
    for (int i = 0; i < 8; i++) { acc2[i][0] = 0ull; acc2[i][1] = 0ull; }
    float ssacc = 0.0f;

    const int p = p0 + px_l;
    const bool pOK = p < NPIX;

    for (int kc = 0; kc < CIN; kc += 16) {
        __syncthreads();
#pragma unroll
        for (int r = 0; r < 8; r++) {
            int k = kk2 + 2 * r;
            float v = pOK ? Xb[(kc + k) * NPIX + p] : 0.0f;
            sX[k][px_l] = v;
            if (COMPUTE_SS) ssacc += v * v;
        }
        {
            int co_l = tid >> 2, ci0 = (tid & 3) * 4;
            const float* wp = W + (long long)(co0 + co_l) * CIN + kc + ci0;
#pragma unroll
            for (int r = 0; r < 4; r++) sW[co_l][ci0 + r] = wp[r];
        }
        __syncthreads();
#pragma unroll
        for (int k = 0; k < 16; k++) {
            const ulonglong2 xv = *reinterpret_cast<const ulonglong2*>(&sX[k][px_g * 4]);
#pragma unroll
            for (int i = 0; i < 8; i++) {
                uint64_t wv = bcast2(sW[co_g * 8 + i][k]);
                ffma2(acc2[i][0], wv, xv.x);
                ffma2(acc2[i][1], wv, xv.y);
            }
        }
    }

    if (COMPUTE_SS) {
        __syncthreads();
        if (kk2 == 0) sF[px_l] = ssacc;
        __syncthreads();
        if (kk2 == 1) sF[px_l] += ssacc;
        __syncthreads();
        if (tid < 128) sF[tid] = 1.0f / (sqrtf(sF[tid]) + EPSC);
        __syncthreads();
    } else {
        __syncthreads();
    }

    float s1[8], s2[8];
#pragma unroll
    for (int i = 0; i < 8; i++) {
        int co_l = co_g * 8 + i;
        long long base = ((long long)(b * outC + co0 + co_l)) * NPIX;
        float wf = sWF[co_l];
        float yv[4];
        unpack2(acc2[i][0], yv[0], yv[1]);
        unpack2(acc2[i][1], yv[2], yv[3]);
        float a = 0.0f, a2 = 0.0f;
#pragma unroll
        for (int j = 0; j < 4; j++) {
            int px = px_g * 4 + j;
            int pp = p0 + px;
            if (pp < NPIX) {
                Y[base + pp]   = yv[j];
                COS[base + pp] = yv[j] * wf * sF[px];
                a += yv[j]; a2 += yv[j] * yv[j];
            }
        }
        s1[i] = a; s2[i] = a2;
    }
#pragma unroll
    for (int i = 0; i < 8; i++) {
#pragma unroll
        for (int off = 16; off; off >>= 1) {
            s1[i] += __shfl_xor_sync(0xffffffffu, s1[i], off);
            s2[i] += __shfl_xor_sync(0xffffffffu, s2[i], off);
        }
    }
    if (px_g == 0) {
#pragma unroll
        for (int i = 0; i < 8; i++) {
            int c = co0 + co_g * 8 + i;
            atomicAdd(&stbase[2 * c],     s1[i]);
            atomicAdd(&stbase[2 * c + 1], s2[i]);
        }
    }
}

// ---------------- 3x3 conv (64->64, pad 1), f32x2 over co-pairs --------------
// Block: one image row (56 px) x 64 out-channels. Grid: (56, B)
__global__ void __launch_bounds__(128) conv3x3_k(
    const float* __restrict__ Hin, const float* __restrict__ W2,
    const float* __restrict__ wn, const float* __restrict__ xnorm,
    float* __restrict__ Y, float* __restrict__ COS, float* __restrict__ stbase)
{
    __shared__ float sX[16][60];
    __shared__ float sW[48][64];
    __shared__ float sWF[64];
    __shared__ float sF[56];

    const int yy = blockIdx.x;
    const int b  = blockIdx.y;
    const int tid = threadIdx.x;
    const int cg = tid >> 3;   // 16 groups x 4 co
    const int pg = tid & 7;    // 8 groups x 7 px

    if (tid < 64) sWF[tid] = 1.0f / (wn[tid] + EPSC);
    if (tid < 56) sF[tid]  = 1.0f / (xnorm[b * NPIX + yy * HW + tid] + EPSC);

    uint64_t acc2[2][7];
#pragma unroll
    for (int i = 0; i < 2; i++)
#pragma unroll
        for (int j = 0; j < 7; j++) acc2[i][j] = 0ull;

    for (int ky = 0; ky < 3; ky++) {
        int row = yy + ky - 1;
        bool rok = (unsigned)row < (unsigned)HW;
        for (int cc = 0; cc < 4; cc++) {
            int ci0 = cc * 16;
            __syncthreads();
            for (int f = tid; f < 16 * 58; f += 128) {
                int ci = f / 58, xx = f % 58;
                int col = xx - 1;
                float v = 0.0f;
                if (rok && (unsigned)col < (unsigned)HW)
                    v = Hin[((long long)(b * C_MID + ci0 + ci)) * NPIX + row * HW + col];
                sX[ci][xx] = v;
            }
            for (int f = tid; f < 16 * 3 * 64; f += 128) {
                int co = f & 63; int rest = f >> 6;
                int ci = rest / 3, kx = rest % 3;
                sW[ci * 3 + kx][co] = W2[(long long)co * 576 + (ci0 + ci) * 9 + ky * 3 + kx];
            }
            __syncthreads();
            if (!rok) continue;
#pragma unroll
            for (int ci = 0; ci < 16; ci++) {
#pragma unroll
                for (int kx = 0; kx < 3; kx++) {
                    const uint64_t w01 = *reinterpret_cast<const uint64_t*>(&sW[ci * 3 + kx][cg * 4]);
                    const uint64_t w23 = *reinterpret_cast<const uint64_t*>(&sW[ci * 3 + kx][cg * 4 + 2]);
#pragma unroll
                    for (int j = 0; j < 7; j++) {
                        uint64_t xv = bcast2(sX[ci][pg * 7 + j + kx]);
                        ffma2(acc2[0][j], w01, xv);
                        ffma2(acc2[1][j], w23, xv);
                    }
                }
            }
        }
    }

    float accf[4][7];
#pragma unroll
    for (int j = 0; j < 7; j++) {
        unpack2(acc2[0][j], accf[0][j], accf[1][j]);
        unpack2(acc2[1][j], accf[2][j], accf[3][j]);
    }

    float s1[4], s2[4];
#pragma unroll
    for (int i = 0; i < 4; i++) {
        int co = cg * 4 + i;
        long long base = ((long long)(b * C_MID + co)) * NPIX + yy * HW;
        float wf = sWF[co];
        float a = 0.0f, a2 = 0.0f;
#pragma unroll
        for (int j = 0; j < 7; j++) {
            int x = pg * 7 + j;
            float yv = accf[i][j];
            Y[base + x]   = yv;
            COS[base + x] = yv * wf * sF[x];
            a += yv; a2 += yv * yv;
        }
        s1[i] = a; s2[i] = a2;
    }
#pragma unroll
    for (int i = 0; i < 4; i++) {
#pragma unroll
        for (int off = 4; off; off >>= 1) {
            s1[i] += __shfl_xor_sync(0xffffffffu, s1[i], off);
            s2[i] += __shfl_xor_sync(0xffffffffu, s2[i], off);
        }
    }
    if (pg == 0) {
#pragma unroll
        for (int i = 0; i < 4; i++) {
            int c = cg * 4 + i;
            atomicAdd(&stbase[2 * c],     s1[i]);
            atomicAdd(&stbase[2 * c + 1], s2[i]);
        }
    }
}

// ---------------- 3x3 box sum of ss -> sqrt (x_norm for conv2) ----------------
__global__ void box3_k(const float* __restrict__ ss, float* __restrict__ xn) {
    int gid = blockIdx.x * 256 + threadIdx.x;
    if (gid >= NBP) return;
    int b = gid / NPIX, p = gid % NPIX;
    int y = p / HW, x = p % HW;
    float s = 0.0f;
    for (int dy = -1; dy <= 1; dy++) {
        int yy = y + dy;
        if ((unsigned)yy >= (unsigned)HW) continue;
        for (int dx = -1; dx <= 1; dx++) {
            int xx = x + dx;
            if ((unsigned)xx >= (unsigned)HW) continue;
            s += ss[b * NPIX + yy * HW + xx];
        }
    }
    xn[gid] = sqrtf(s);
}

// ---------------- fused Gumbel-argmax sampling (stages 1 & 2) ----------------
__global__ void sample_k(const float* __restrict__ cosb,
                         int C, uint32_t k0, uint32_t k1, int units, float scale)
{
    int wid  = (blockIdx.x * blockDim.x + threadIdx.x) >> 5;
    int lane = threadIdx.x & 31;
    if (wid >= units) return;
    int c = wid % C, b = (wid / C) % NB;
    const float* plane = cosb + (long long)(b * C + c) * NPIX;
    uint32_t ebase = (uint32_t)wid * NPIX;

    float bv = -1e30f;
    int bi = 0;
    for (int p = lane; p < NPIX; p += 32) {
        uint32_t o0, o1;
        threefry2x32_dev(k0, k1, 0u, ebase + (uint32_t)p, o0, o1);
        float v = fmaf(plane[p], 2.0f, gumbel_from_bits(o0 ^ o1));
        if (v > bv) { bv = v; bi = p; }
    }
#pragma unroll
    for (int off = 16; off; off >>= 1) {
        float ov = __shfl_xor_sync(0xffffffffu, bv, off);
        int   oi = __shfl_xor_sync(0xffffffffu, bi, off);
        if (ov > bv || (ov == bv && oi < bi)) { bv = ov; bi = oi; }
    }
    int wy = bi / HW, wx = bi - wy * HW;
    float s = 0.0f;
    for (int t = lane; t < 121; t += 32) {
        int dy = t / 11 - 5, dx = t - (t / 11) * 11 - 5;
        int yyp = wy + dy, xxp = wx + dx;
        if ((unsigned)yyp < (unsigned)HW && (unsigned)xxp < (unsigned)HW)
            s += plane[yyp * HW + xxp];
    }
#pragma unroll
    for (int off = 16; off; off >>= 1) s += __shfl_xor_sync(0xffffffffu, s, off);
    if (lane == 0) atomicAdd(&g_acc[0], s * scale);
}

// ---------------- stage-3 argmax using precomputed gumbels -------------------
// warp order: s fastest so the 5 samples of one (b,c) plane are L2-adjacent
__global__ void argmax3_k(const float* __restrict__ cosb, const float* __restrict__ gum,
                          float scale)
{
    int w    = (blockIdx.x * blockDim.x + threadIdx.x) >> 5;
    int lane = threadIdx.x & 31;
    if (w >= 20480) return;
    int s5 = w % 5;
    int bc = w / 5;               // 0..4095
    int c  = bc & 255, b = bc >> 8;
    int unit = (s5 * NB + b) * C_IN + c;
    const float* plane = cosb + (long long)(b * C_IN + c) * NPIX;
    const float* gp    = gum  + (long long)unit * NPIX;

    float bv = -1e30f;
    int bi = 0;
    for (int p = lane; p < NPIX; p += 32) {
        float v = fmaf(__ldg(plane + p), 2.0f, __ldg(gp + p));
        if (v > bv) { bv = v; bi = p; }
    }
#pragma unroll
    for (int off = 16; off; off >>= 1) {
        float ov = __shfl_xor_sync(0xffffffffu, bv, off);
        int   oi = __shfl_xor_sync(0xffffffffu, bi, off);
        if (ov > bv || (ov == bv && oi < bi)) { bv = ov; bi = oi; }
    }
    int wy = bi / HW, wx = bi - wy * HW;
    float s = 0.0f;
    for (int t = lane; t < 121; t += 32) {
        int dy = t / 11 - 5, dx = t - (t / 11) * 11 - 5;
        int yyp = wy + dy, xxp = wx + dx;
        if ((unsigned)yyp < (unsigned)HW && (unsigned)xxp < (unsigned)HW)
            s += plane[yyp * HW + xxp];
    }
#pragma unroll
    for (int off = 16; off; off >>= 1) s += __shfl_xor_sync(0xffffffffu, s, off);
    if (lane == 0) atomicAdd(&g_acc[0], s * scale);
}

// ---------------- BN apply (+relu, + per-pixel sumsq) ------------------------
template<bool SQRT_SS>
__global__ void bnapply_k(const float* __restrict__ Y,
                          const float* __restrict__ gam, const float* __restrict__ bet,
                          const float* __restrict__ st,
                          float* __restrict__ Hout, float* __restrict__ ssout)
{
    __shared__ float sc[C_MID], sh[C_MID];
    if (threadIdx.x < C_MID) {
        int c = threadIdx.x;
        float m = st[2 * c] / (float)NBP;
        float v = st[2 * c + 1] / (float)NBP - m * m;
        float is = rsqrtf(v + BNEPS);
        sc[c] = gam[c] * is;
        sh[c] = bet[c] - m * gam[c] * is;
    }
    __syncthreads();
    int gid = blockIdx.x * 256 + threadIdx.x;
    if (gid >= NBP) return;
    int b = gid / NPIX, p = gid - b * NPIX;
    long long base = (long long)b * C_MID * NPIX + p;
    float ss = 0.0f;
    for (int c = 0; c < C_MID; c++) {
        float v = Y[base + c * NPIX];
        float h = fmaxf(fmaf(v, sc[c], sh[c]), 0.0f);
        Hout[base + c * NPIX] = h;
        ss += h * h;
    }
    ssout[gid] = SQRT_SS ? sqrtf(ss) : ss;
}

// ---------------- Final: BN3 + residual + ReLU ----------------
__global__ void final_k(const float* __restrict__ Y, const float* __restrict__ X,
                        const float* __restrict__ gam, const float* __restrict__ bet,
                        const float* __restrict__ st, float* __restrict__ out)
{
    __shared__ float sc[C_IN], sh[C_IN];
    {
        int c = threadIdx.x;
        float m = st[2 * c] / (float)NBP;
        float v = st[2 * c + 1] / (float)NBP - m * m;
        float is = rsqrtf(v + BNEPS);
        sc[c] = gam[c] * is;
        sh[c] = bet[c] - m * gam[c] * is;
    }
    __syncthreads();
    int gid = blockIdx.x * 256 + threadIdx.x;
    int c = (gid / NPIX) & 255;
    out[gid] = fmaxf(fmaf(Y[gid], sc[c], sh[c]) + X[gid], 0.0f);
}

__global__ void writeacc_k(float* out) { out[NOUT_MAIN] = g_acc[0]; }

// ---------------- host: streams/events (created once, before any capture) ----
static cudaStream_t g_side = nullptr;
static cudaEvent_t  g_evRoot, g_evC1, g_evC2, g_evC3, g_evJoin;
static void ensure_streams() {
    if (!g_side) {
        cudaStreamCreateWithFlags(&g_side, cudaStreamNonBlocking);
        cudaEventCreateWithFlags(&g_evRoot, cudaEventDisableTiming);
        cudaEventCreateWithFlags(&g_evC1,   cudaEventDisableTiming);
        cudaEventCreateWithFlags(&g_evC2,   cudaEventDisableTiming);
        cudaEventCreateWithFlags(&g_evC3,   cudaEventDisableTiming);
        cudaEventCreateWithFlags(&g_evJoin, cudaEventDisableTiming);
    }
}
static struct StreamInit { StreamInit() { ensure_streams(); } } g_streamInit;

static void host_keys(uint32_t* K) {
    // Partitionable (foldlike) split of key(42) = (0, 42)
    threefry2x32(0u, 42u, 0u, 0u, K[0], K[1]);   // k0
    threefry2x32(0u, 42u, 0u, 1u, K[2], K[3]);   // k1
    threefry2x32(0u, 42u, 0u, 2u, K[4], K[5]);   // k2
}

extern "C" void kernel_launch(void* const* d_in, const int* in_sizes, int n_in,
                              void* d_out, int out_size)
{
    ensure_streams();

    const float* x  = (const float*)d_in[0];
    const float* w1 = (const float*)d_in[1];
    const float* w2 = (const float*)d_in[2];
    const float* w3 = (const float*)d_in[3];
    const float* g1 = (const float*)d_in[4];
    const float* b1 = (const float*)d_in[5];
    const float* g2 = (const float*)d_in[6];
    const float* b2 = (const float*)d_in[7];
    const float* g3 = (const float*)d_in[8];
    const float* b3 = (const float*)d_in[9];
    float* out = (float*)d_out;

    float *yP, *c1P, *c2P, *c3P, *g3P, *hP, *ssP, *xnP, *wnP, *stP;
    cudaGetSymbolAddress((void**)&yP,  g_y);
    cudaGetSymbolAddress((void**)&c1P, g_cos1);
    cudaGetSymbolAddress((void**)&c2P, g_cos2);
    cudaGetSymbolAddress((void**)&c3P, g_cos3);
    cudaGetSymbolAddress((void**)&g3P, g_g3);
    cudaGetSymbolAddress((void**)&hP,  g_h);
    cudaGetSymbolAddress((void**)&ssP, g_ss);
    cudaGetSymbolAddress((void**)&xnP, g_xn);
    cudaGetSymbolAddress((void**)&wnP, g_wn);
    cudaGetSymbolAddress((void**)&stP, g_st);

    uint32_t K[6]; host_keys(K);

    // Fork side stream off the (possibly capturing) main stream.
    cudaEventRecord(g_evRoot, 0);
    cudaStreamWaitEvent(g_side, g_evRoot, 0);

    // SIDE: precompute stage-3 gumbels (data-independent, big) right away.
    hash3_k<<<(NG3 + 255) / 256, 256, 0, g_side>>>(K[4], K[5], g3P);

    // MAIN: init + stage 1
    wnorm_all_k<<<384, 256>>>(w1, w2, w3);
    conv1x1_k<C_IN, true><<<dim3(25, NB, 1), 256>>>(x, w1, wnP, nullptr, yP, c1P, stP, C_MID);
    cudaEventRecord(g_evC1, 0);
    bnapply_k<false><<<196, 256>>>(yP, g1, b1, stP, hP, ssP);
    box3_k<<<196, 256>>>(ssP, xnP);

    // SIDE: stage-1 sampler (after conv1's cosine is ready)
    cudaStreamWaitEvent(g_side, g_evC1, 0);
    sample_k<<<640, 256, 0, g_side>>>(c1P, C_MID, K[0], K[1], 5120, 1.0f / (5120.0f * 121.0f));

    // MAIN: stage 2
    conv3x3_k<<<dim3(HW, NB), 128>>>(hP, w2, wnP + 64, xnP, yP, c2P, stP + 128);
    cudaEventRecord(g_evC2, 0);
    bnapply_k<true><<<196, 256>>>(yP, g2, b2, stP + 128, hP, ssP);  // ssP <- sqrt(sum h^2)

    // SIDE: stage-2 sampler
    cudaStreamWaitEvent(g_side, g_evC2, 0);
    sample_k<<<640, 256, 0, g_side>>>(c2P, C_MID, K[2], K[3], 5120, 1.0f / (5120.0f * 121.0f));

    // MAIN: stage 3
    conv1x1_k<C_MID, false><<<dim3(25, NB, 4), 256>>>(hP, w3, wnP + 128, ssP, yP, c3P, stP + 256, C_IN);
    cudaEventRecord(g_evC3, 0);
    final_k<<<NOUT_MAIN / 256, 256>>>(yP, x, g3, b3, stP + 256, out);

    // SIDE: stage-3 argmax with precomputed gumbels
    cudaStreamWaitEvent(g_side, g_evC3, 0);
    argmax3_k<<<2560, 256, 0, g_side>>>(c3P, g3P, 1.0f / (20480.0f * 121.0f));
    cudaEventRecord(g_evJoin, g_side);

    // MAIN: join and emit acc
    cudaStreamWaitEvent(0, g_evJoin, 0);
    if (out_size > NOUT_MAIN) writeacc_k<<<1, 1>>>(out);
}

// round 5
// speedup vs baseline: 1.1331x; 1.1331x over previous
#include <cuda_runtime.h>
#include <stdint.h>
#include <math.h>

// Problem constants
#define NB    16
#define HW    56
#define NPIX  3136           // 56*56
#define NBP   50176          // NB*NPIX
#define C_IN  256
#define C_MID 64
#define EPSC  1e-6f
#define BNEPS 1e-5f
#define NOUT_MAIN 12845056   // 16*256*56*56

// ---------------- scratch (__device__ globals; no allocation) ----------------
__device__ float g_y   [NOUT_MAIN];   // conv output (pre-BN), per stage
__device__ float g_cos1[C_MID*NBP];   // cosine stage 1
__device__ float g_cos2[C_MID*NBP];   // cosine stage 2
__device__ float g_cos3[NOUT_MAIN];   // cosine stage 3
__device__ float g_h   [C_MID*NBP];   // post-BN/ReLU activations (h1, then h2)
__device__ float g_ss  [NBP];         // per-pixel sum of squares (or sqrt thereof)
__device__ float g_xn  [NBP];         // x_norm for conv2 (sqrt of 3x3 box sum)
__device__ float g_wn  [512];         // weight Frobenius norms (64 + 64 + 256)
__device__ float g_st  [768];         // BN sums/sumsq per stage
__device__ float g_acc [1];

// ---------------- f32x2 packed math ----------------
__device__ __forceinline__ void ffma2(uint64_t& d, uint64_t a, uint64_t b) {
    asm("fma.rn.f32x2 %0, %1, %2, %0;" : "+l"(d) : "l"(a), "l"(b));
}
__device__ __forceinline__ uint64_t bcast2(float w) {
    uint64_t r; asm("mov.b64 %0, {%1, %1};" : "=l"(r) : "f"(w)); return r;
}
__device__ __forceinline__ void unpack2(uint64_t v, float& lo, float& hi) {
    asm("mov.b64 {%0, %1}, %2;" : "=f"(lo), "=f"(hi) : "l"(v));
}

// ---------------- threefry2x32 (JAX-exact, partitionable mode) ----------------
__host__ __device__ __forceinline__ uint32_t rotl32(uint32_t x, int r) {
    return (x << r) | (x >> (32 - r));
}

__host__ __device__ __forceinline__ void threefry2x32(
    uint32_t k0, uint32_t k1, uint32_t c0, uint32_t c1, uint32_t& o0, uint32_t& o1)
{
    uint32_t ks0 = k0, ks1 = k1, ks2 = k0 ^ k1 ^ 0x1BD11BDAu;
    uint32_t x0 = c0 + ks0, x1 = c1 + ks1;
#define TF_R(r) { x0 += x1; x1 = rotl32(x1, r); x1 ^= x0; }
    TF_R(13) TF_R(15) TF_R(26) TF_R(6)   x0 += ks1; x1 += ks2 + 1u;
    TF_R(17) TF_R(29) TF_R(16) TF_R(24)  x0 += ks2; x1 += ks0 + 2u;
    TF_R(13) TF_R(15) TF_R(26) TF_R(6)   x0 += ks0; x1 += ks1 + 3u;
    TF_R(17) TF_R(29) TF_R(16) TF_R(24)  x0 += ks1; x1 += ks2 + 4u;
    TF_R(13) TF_R(15) TF_R(26) TF_R(6)   x0 += ks2; x1 += ks0 + 5u;
#undef TF_R
    o0 = x0; o1 = x1;
}

// Device version: rotate via widening mul (fma pipe) -> round = IADD3 + IMAD.WIDE + LOP3.
__device__ __forceinline__ void threefry2x32_dev(
    uint32_t k0, uint32_t k1, uint32_t c0, uint32_t c1, uint32_t& o0, uint32_t& o1)
{
    uint32_t ks0 = k0, ks1 = k1, ks2 = k0 ^ k1 ^ 0x1BD11BDAu;
    uint32_t x0 = c0 + ks0, x1 = c1 + ks1;
#define TF_R(r) { x0 += x1; \
    uint64_t m = (uint64_t)x1 * ((uint64_t)(1u << (r))); \
    x1 = ((uint32_t)m | (uint32_t)(m >> 32)) ^ x0; }
    TF_R(13) TF_R(15) TF_R(26) TF_R(6)   x0 += ks1; x1 += ks2 + 1u;
    TF_R(17) TF_R(29) TF_R(16) TF_R(24)  x0 += ks2; x1 += ks0 + 2u;
    TF_R(13) TF_R(15) TF_R(26) TF_R(6)   x0 += ks0; x1 += ks1 + 3u;
    TF_R(17) TF_R(29) TF_R(16) TF_R(24)  x0 += ks1; x1 += ks2 + 4u;
    TF_R(13) TF_R(15) TF_R(26) TF_R(6)   x0 += ks2; x1 += ks0 + 5u;
#undef TF_R
    o0 = x0; o1 = x1;
}

__device__ __forceinline__ float gumbel_from_bits(uint32_t bits) {
    float u = __uint_as_float(0x3f800000u | (bits >> 9)) - 1.0f;
    u = fmaxf(u, 1.17549435e-38f);
    return -__logf(-__logf(u));
}

// ---------------- combined init + weight norms ----------------
// Grid 384: rows 0-63 -> w1 (len 256); 64-127 -> w2 (len 576); 128-383 -> w3 (len 64)
__global__ void wnorm_all_k(const float* __restrict__ w1, const float* __restrict__ w2,
                            const float* __restrict__ w3) {
    __shared__ float sm[256];
    int row = blockIdx.x;
    const float* w; int len; int r;
    if (row < 64)       { w = w1; len = 256; r = row; }
    else if (row < 128) { w = w2; len = 576; r = row - 64; }
    else                { w = w3; len = 64;  r = row - 128; }
    float s = 0.0f;
    for (int i = threadIdx.x; i < len; i += 256) {
        float v = w[(long long)r * len + i];
        s += v * v;
    }
    sm[threadIdx.x] = s; __syncthreads();
    for (int st = 128; st > 0; st >>= 1) {
        if (threadIdx.x < st) sm[threadIdx.x] += sm[threadIdx.x + st];
        __syncthreads();
    }
    if (threadIdx.x == 0) g_wn[row] = sqrtf(sm[0]);
    if (row == 0) {
        for (int i = threadIdx.x; i < 768; i += 256) g_st[i] = 0.0f;
        if (threadIdx.x == 0) g_acc[0] = 0.0f;
    }
}

// ---------------- 1x1 conv GEMM (f32x2) + cosine + fused BN stats ------------
// Block: 64 out-channels x 128 pixels.  Grid: (25, B, outC/64)
template<int CIN, bool COMPUTE_SS>
__global__ void __launch_bounds__(256) conv1x1_k(
    const float* __restrict__ X, const float* __restrict__ W,
    const float* __restrict__ wn, const float* __restrict__ xn,
    float* __restrict__ Y, float* __restrict__ COS,
    float* __restrict__ stbase, int outC)
{
    __shared__ float sX[16][128];
    __shared__ float sW[64][17];
    __shared__ float sF[128];
    __shared__ float sWF[64];

    const int tid  = threadIdx.x;
    const int p0   = blockIdx.x * 128;
    const int b    = blockIdx.y;
    const int co0  = blockIdx.z * 64;
    const int px_l = tid & 127, kk2 = tid >> 7;
    const int co_g = tid >> 5,  px_g = tid & 31;

    const float* Xb = X + (long long)b * CIN * NPIX;

    if (!COMPUTE_SS) {
        if (tid < 128) {
            int pp = p0 + tid;
            float v = (pp < NPIX) ? xn[b * NPIX + pp] : 1.0f;
            sF[tid] = 1.0f / (v + EPSC);
        }
    }
    if (tid < 64) sWF[tid] = 1.0f / (wn[co0 + tid] + EPSC);

    uint64_t acc2[8][2];
#pragma unroll
    for (int i = 0; i < 8; i++) { acc2[i][0] = 0ull; acc2[i][1] = 0ull; }
    float ssacc = 0.0f;

    const int p = p0 + px_l;
    const bool pOK = p < NPIX;

    for (int kc = 0; kc < CIN; kc += 16) {
        __syncthreads();
#pragma unroll
        for (int r = 0; r < 8; r++) {
            int k = kk2 + 2 * r;
            float v = pOK ? Xb[(kc + k) * NPIX + p] : 0.0f;
            sX[k][px_l] = v;
            if (COMPUTE_SS) ssacc += v * v;
        }
        {
            int co_l = tid >> 2, ci0 = (tid & 3) * 4;
            const float* wp = W + (long long)(co0 + co_l) * CIN + kc + ci0;
#pragma unroll
            for (int r = 0; r < 4; r++) sW[co_l][ci0 + r] = wp[r];
        }
        __syncthreads();
#pragma unroll
        for (int k = 0; k < 16; k++) {
            const ulonglong2 xv = *reinterpret_cast<const ulonglong2*>(&sX[k][px_g * 4]);
#pragma unroll
            for (int i = 0; i < 8; i++) {
                uint64_t wv = bcast2(sW[co_g * 8 + i][k]);
                ffma2(acc2[i][0], wv, xv.x);
                ffma2(acc2[i][1], wv, xv.y);
            }
        }
    }

    if (COMPUTE_SS) {
        __syncthreads();
        if (kk2 == 0) sF[px_l] = ssacc;
        __syncthreads();
        if (kk2 == 1) sF[px_l] += ssacc;
        __syncthreads();
        if (tid < 128) sF[tid] = 1.0f / (sqrtf(sF[tid]) + EPSC);
        __syncthreads();
    } else {
        __syncthreads();
    }

    float s1[8], s2[8];
#pragma unroll
    for (int i = 0; i < 8; i++) {
        int co_l = co_g * 8 + i;
        long long base = ((long long)(b * outC + co0 + co_l)) * NPIX;
        float wf = sWF[co_l];
        float yv[4];
        unpack2(acc2[i][0], yv[0], yv[1]);
        unpack2(acc2[i][1], yv[2], yv[3]);
        float a = 0.0f, a2 = 0.0f;
#pragma unroll
        for (int j = 0; j < 4; j++) {
            int px = px_g * 4 + j;
            int pp = p0 + px;
            if (pp < NPIX) {
                Y[base + pp]   = yv[j];
                COS[base + pp] = yv[j] * wf * sF[px];
                a += yv[j]; a2 += yv[j] * yv[j];
            }
        }
        s1[i] = a; s2[i] = a2;
    }
#pragma unroll
    for (int i = 0; i < 8; i++) {
#pragma unroll
        for (int off = 16; off; off >>= 1) {
            s1[i] += __shfl_xor_sync(0xffffffffu, s1[i], off);
            s2[i] += __shfl_xor_sync(0xffffffffu, s2[i], off);
        }
    }
    if (px_g == 0) {
#pragma unroll
        for (int i = 0; i < 8; i++) {
            int c = co0 + co_g * 8 + i;
            atomicAdd(&stbase[2 * c],     s1[i]);
            atomicAdd(&stbase[2 * c + 1], s2[i]);
        }
    }
}

// ---------------- 3x3 conv (64->64, pad 1), f32x2 over co-pairs --------------
// Block: one image row (56 px) x 64 out-channels. Grid: (56, B)
__global__ void __launch_bounds__(128) conv3x3_k(
    const float* __restrict__ Hin, const float* __restrict__ W2,
    const float* __restrict__ wn, const float* __restrict__ xnorm,
    float* __restrict__ Y, float* __restrict__ COS, float* __restrict__ stbase)
{
    __shared__ float sX[16][60];
    __shared__ float sW[48][64];
    __shared__ float sWF[64];
    __shared__ float sF[56];

    const int yy = blockIdx.x;
    const int b  = blockIdx.y;
    const int tid = threadIdx.x;
    const int cg = tid >> 3;   // 16 groups x 4 co
    const int pg = tid & 7;    // 8 groups x 7 px

    if (tid < 64) sWF[tid] = 1.0f / (wn[tid] + EPSC);
    if (tid < 56) sF[tid]  = 1.0f / (xnorm[b * NPIX + yy * HW + tid] + EPSC);

    uint64_t acc2[2][7];
#pragma unroll
    for (int i = 0; i < 2; i++)
#pragma unroll
        for (int j = 0; j < 7; j++) acc2[i][j] = 0ull;

    for (int ky = 0; ky < 3; ky++) {
        int row = yy + ky - 1;
        bool rok = (unsigned)row < (unsigned)HW;
        for (int cc = 0; cc < 4; cc++) {
            int ci0 = cc * 16;
            __syncthreads();
            for (int f = tid; f < 16 * 58; f += 128) {
                int ci = f / 58, xx = f % 58;
                int col = xx - 1;
                float v = 0.0f;
                if (rok && (unsigned)col < (unsigned)HW)
                    v = Hin[((long long)(b * C_MID + ci0 + ci)) * NPIX + row * HW + col];
                sX[ci][xx] = v;
            }
            for (int f = tid; f < 16 * 3 * 64; f += 128) {
                int co = f & 63; int rest = f >> 6;
                int ci = rest / 3, kx = rest % 3;
                sW[ci * 3 + kx][co] = W2[(long long)co * 576 + (ci0 + ci) * 9 + ky * 3 + kx];
            }
            __syncthreads();
            if (!rok) continue;
#pragma unroll
            for (int ci = 0; ci < 16; ci++) {
#pragma unroll
                for (int kx = 0; kx < 3; kx++) {
                    const uint64_t w01 = *reinterpret_cast<const uint64_t*>(&sW[ci * 3 + kx][cg * 4]);
                    const uint64_t w23 = *reinterpret_cast<const uint64_t*>(&sW[ci * 3 + kx][cg * 4 + 2]);
#pragma unroll
                    for (int j = 0; j < 7; j++) {
                        uint64_t xv = bcast2(sX[ci][pg * 7 + j + kx]);
                        ffma2(acc2[0][j], w01, xv);
                        ffma2(acc2[1][j], w23, xv);
                    }
                }
            }
        }
    }

    float accf[4][7];
#pragma unroll
    for (int j = 0; j < 7; j++) {
        unpack2(acc2[0][j], accf[0][j], accf[1][j]);
        unpack2(acc2[1][j], accf[2][j], accf[3][j]);
    }

    float s1[4], s2[4];
#pragma unroll
    for (int i = 0; i < 4; i++) {
        int co = cg * 4 + i;
        long long base = ((long long)(b * C_MID + co)) * NPIX + yy * HW;
        float wf = sWF[co];
        float a = 0.0f, a2 = 0.0f;
#pragma unroll
        for (int j = 0; j < 7; j++) {
            int x = pg * 7 + j;
            float yv = accf[i][j];
            Y[base + x]   = yv;
            COS[base + x] = yv * wf * sF[x];
            a += yv; a2 += yv * yv;
        }
        s1[i] = a; s2[i] = a2;
    }
#pragma unroll
    for (int i = 0; i < 4; i++) {
#pragma unroll
        for (int off = 4; off; off >>= 1) {
            s1[i] += __shfl_xor_sync(0xffffffffu, s1[i], off);
            s2[i] += __shfl_xor_sync(0xffffffffu, s2[i], off);
        }
    }
    if (pg == 0) {
#pragma unroll
        for (int i = 0; i < 4; i++) {
            int c = cg * 4 + i;
            atomicAdd(&stbase[2 * c],     s1[i]);
            atomicAdd(&stbase[2 * c + 1], s2[i]);
        }
    }
}

// ---------------- 3x3 box sum of ss -> sqrt (x_norm for conv2) ----------------
__global__ void box3_k(const float* __restrict__ ss, float* __restrict__ xn) {
    int gid = blockIdx.x * 256 + threadIdx.x;
    if (gid >= NBP) return;
    int b = gid / NPIX, p = gid % NPIX;
    int y = p / HW, x = p % HW;
    float s = 0.0f;
    for (int dy = -1; dy <= 1; dy++) {
        int yy = y + dy;
        if ((unsigned)yy >= (unsigned)HW) continue;
        for (int dx = -1; dx <= 1; dx++) {
            int xx = x + dx;
            if ((unsigned)xx >= (unsigned)HW) continue;
            s += ss[b * NPIX + yy * HW + xx];
        }
    }
    xn[gid] = sqrtf(s);
}

// ---------------- fused Gumbel-argmax sampling + on-the-fly 11x11 mean -------
// One warp per (s,b,c) unit; hash in registers, no gumbel storage.
__global__ void sample_k(const float* __restrict__ cosb,
                         int C, uint32_t k0, uint32_t k1, int units, float scale)
{
    int wid  = (blockIdx.x * blockDim.x + threadIdx.x) >> 5;
    int lane = threadIdx.x & 31;
    if (wid >= units) return;
    int c = wid % C, b = (wid / C) % NB;
    const float* plane = cosb + (long long)(b * C + c) * NPIX;
    uint32_t ebase = (uint32_t)wid * NPIX;

    float bv = -1e30f;
    int bi = 0;
    for (int p = lane; p < NPIX; p += 32) {
        uint32_t o0, o1;
        threefry2x32_dev(k0, k1, 0u, ebase + (uint32_t)p, o0, o1);
        float v = fmaf(plane[p], 2.0f, gumbel_from_bits(o0 ^ o1));
        if (v > bv) { bv = v; bi = p; }
    }
#pragma unroll
    for (int off = 16; off; off >>= 1) {
        float ov = __shfl_xor_sync(0xffffffffu, bv, off);
        int   oi = __shfl_xor_sync(0xffffffffu, bi, off);
        if (ov > bv || (ov == bv && oi < bi)) { bv = ov; bi = oi; }
    }
    int wy = bi / HW, wx = bi - wy * HW;
    float s = 0.0f;
    for (int t = lane; t < 121; t += 32) {
        int dy = t / 11 - 5, dx = t - (t / 11) * 11 - 5;
        int yyp = wy + dy, xxp = wx + dx;
        if ((unsigned)yyp < (unsigned)HW && (unsigned)xxp < (unsigned)HW)
            s += plane[yyp * HW + xxp];
    }
#pragma unroll
    for (int off = 16; off; off >>= 1) s += __shfl_xor_sync(0xffffffffu, s, off);
    if (lane == 0) atomicAdd(&g_acc[0], s * scale);
}

// ---------------- BN apply (+relu, + per-pixel sumsq) ------------------------
template<bool SQRT_SS>
__global__ void bnapply_k(const float* __restrict__ Y,
                          const float* __restrict__ gam, const float* __restrict__ bet,
                          const float* __restrict__ st,
                          float* __restrict__ Hout, float* __restrict__ ssout)
{
    __shared__ float sc[C_MID], sh[C_MID];
    if (threadIdx.x < C_MID) {
        int c = threadIdx.x;
        float m = st[2 * c] / (float)NBP;
        float v = st[2 * c + 1] / (float)NBP - m * m;
        float is = rsqrtf(v + BNEPS);
        sc[c] = gam[c] * is;
        sh[c] = bet[c] - m * gam[c] * is;
    }
    __syncthreads();
    int gid = blockIdx.x * 256 + threadIdx.x;
    if (gid >= NBP) return;
    int b = gid / NPIX, p = gid - b * NPIX;
    long long base = (long long)b * C_MID * NPIX + p;
    float ss = 0.0f;
    for (int c = 0; c < C_MID; c++) {
        float v = Y[base + c * NPIX];
        float h = fmaxf(fmaf(v, sc[c], sh[c]), 0.0f);
        Hout[base + c * NPIX] = h;
        ss += h * h;
    }
    ssout[gid] = SQRT_SS ? sqrtf(ss) : ss;
}

// ---------------- Final: BN3 + residual + ReLU (float4) ----------------------
__global__ void final_k(const float4* __restrict__ Y4, const float4* __restrict__ X4,
                        const float* __restrict__ gam, const float* __restrict__ bet,
                        const float* __restrict__ st, float4* __restrict__ out4)
{
    __shared__ float sc[C_IN], sh[C_IN];
    {
        int c = threadIdx.x;
        float m = st[2 * c] / (float)NBP;
        float v = st[2 * c + 1] / (float)NBP - m * m;
        float is = rsqrtf(v + BNEPS);
        sc[c] = gam[c] * is;
        sh[c] = bet[c] - m * gam[c] * is;
    }
    __syncthreads();
    int gid = blockIdx.x * 256 + threadIdx.x;     // over NOUT_MAIN/4
    int c = (gid / (NPIX / 4)) & 255;
    float4 y = Y4[gid], x = X4[gid];
    float s = sc[c], h = sh[c];
    float4 o;
    o.x = fmaxf(fmaf(y.x, s, h) + x.x, 0.0f);
    o.y = fmaxf(fmaf(y.y, s, h) + x.y, 0.0f);
    o.z = fmaxf(fmaf(y.z, s, h) + x.z, 0.0f);
    o.w = fmaxf(fmaf(y.w, s, h) + x.w, 0.0f);
    out4[gid] = o;
}

__global__ void writeacc_k(float* out) { out[NOUT_MAIN] = g_acc[0]; }

// ---------------- host: streams/events (created once, before any capture) ----
static cudaStream_t g_side = nullptr;
static cudaEvent_t  g_evRoot, g_evC1, g_evC2, g_evC3, g_evJoin;
static void ensure_streams() {
    if (!g_side) {
        cudaStreamCreateWithFlags(&g_side, cudaStreamNonBlocking);
        cudaEventCreateWithFlags(&g_evRoot, cudaEventDisableTiming);
        cudaEventCreateWithFlags(&g_evC1,   cudaEventDisableTiming);
        cudaEventCreateWithFlags(&g_evC2,   cudaEventDisableTiming);
        cudaEventCreateWithFlags(&g_evC3,   cudaEventDisableTiming);
        cudaEventCreateWithFlags(&g_evJoin, cudaEventDisableTiming);
    }
}
static struct StreamInit { StreamInit() { ensure_streams(); } } g_streamInit;

static void host_keys(uint32_t* K) {
    // Partitionable (foldlike) split of key(42) = (0, 42)
    threefry2x32(0u, 42u, 0u, 0u, K[0], K[1]);   // k0
    threefry2x32(0u, 42u, 0u, 1u, K[2], K[3]);   // k1
    threefry2x32(0u, 42u, 0u, 2u, K[4], K[5]);   // k2
}

extern "C" void kernel_launch(void* const* d_in, const int* in_sizes, int n_in,
                              void* d_out, int out_size)
{
    ensure_streams();

    const float* x  = (const float*)d_in[0];
    const float* w1 = (const float*)d_in[1];
    const float* w2 = (const float*)d_in[2];
    const float* w3 = (const float*)d_in[3];
    const float* g1 = (const float*)d_in[4];
    const float* b1 = (const float*)d_in[5];
    const float* g2 = (const float*)d_in[6];
    const float* b2 = (const float*)d_in[7];
    const float* g3 = (const float*)d_in[8];
    const float* b3 = (const float*)d_in[9];
    float* out = (float*)d_out;

    float *yP, *c1P, *c2P, *c3P, *hP, *ssP, *xnP, *wnP, *stP;
    cudaGetSymbolAddress((void**)&yP,  g_y);
    cudaGetSymbolAddress((void**)&c1P, g_cos1);
    cudaGetSymbolAddress((void**)&c2P, g_cos2);
    cudaGetSymbolAddress((void**)&c3P, g_cos3);
    cudaGetSymbolAddress((void**)&hP,  g_h);
    cudaGetSymbolAddress((void**)&ssP, g_ss);
    cudaGetSymbolAddress((void**)&xnP, g_xn);
    cudaGetSymbolAddress((void**)&wnP, g_wn);
    cudaGetSymbolAddress((void**)&stP, g_st);

    uint32_t K[6]; host_keys(K);

    // Fork side stream off the (possibly capturing) main stream.
    cudaEventRecord(g_evRoot, 0);
    cudaStreamWaitEvent(g_side, g_evRoot, 0);

    // MAIN: init + stage 1
    wnorm_all_k<<<384, 256>>>(w1, w2, w3);
    conv1x1_k<C_IN, true><<<dim3(25, NB, 1), 256>>>(x, w1, wnP, nullptr, yP, c1P, stP, C_MID);
    cudaEventRecord(g_evC1, 0);
    bnapply_k<false><<<196, 256>>>(yP, g1, b1, stP, hP, ssP);
    box3_k<<<196, 256>>>(ssP, xnP);

    // SIDE: stage-1 sampler (640 blocks -> fully resident; co-runs with stage 2)
    cudaStreamWaitEvent(g_side, g_evC1, 0);
    sample_k<<<640, 256, 0, g_side>>>(c1P, C_MID, K[0], K[1], 5120, 1.0f / (5120.0f * 121.0f));

    // MAIN: stage 2
    conv3x3_k<<<dim3(HW, NB), 128>>>(hP, w2, wnP + 64, xnP, yP, c2P, stP + 128);
    cudaEventRecord(g_evC2, 0);
    bnapply_k<true><<<196, 256>>>(yP, g2, b2, stP + 128, hP, ssP);  // ssP <- sqrt(sum h^2)

    // SIDE: stage-2 sampler (co-runs with conv3)
    cudaStreamWaitEvent(g_side, g_evC2, 0);
    sample_k<<<640, 256, 0, g_side>>>(c2P, C_MID, K[2], K[3], 5120, 1.0f / (5120.0f * 121.0f));

    // MAIN: stage 3
    conv1x1_k<C_MID, false><<<dim3(25, NB, 4), 256>>>(hP, w3, wnP + 128, ssP, yP, c3P, stP + 256, C_IN);
    cudaEventRecord(g_evC3, 0);
    final_k<<<NOUT_MAIN / 1024, 256>>>((const float4*)yP, (const float4*)x,
                                       g3, b3, stP + 256, (float4*)out);

    // SIDE: stage-3 fused sampler (co-runs with final_k)
    cudaStreamWaitEvent(g_side, g_evC3, 0);
    sample_k<<<2560, 256, 0, g_side>>>(c3P, C_IN, K[4], K[5], 20480, 1.0f / (20480.0f * 121.0f));
    cudaEventRecord(g_evJoin, g_side);

    // MAIN: join and emit acc
    cudaStreamWaitEvent(0, g_evJoin, 0);
    if (out_size > NOUT_MAIN) writeacc_k<<<1, 1>>>(out);
}